// round 16
// baseline (speedup 1.0000x reference)
#include <cuda_runtime.h>
#include <cstdint>

// Problem dims
#define Lseq  1024
#define Pdim  64
#define Hdim  256
#define OUTD  128
#define GI3H  768      // 3*Hdim

// 32 clusters x 4 CTAs. Cluster: 2 batch rows. CTA: 64 hidden units (192 gate rows).
// 512 threads: tid = u*8 + o. Thread computes gate rows (u, 64+u, 128+u) over its
// 32-column octant for BOTH batches (weights read once). Octants joined by shfl;
// batch folded with one shfl_xor(4): lanes o<4 own batch0, o>=4 own batch1.
// Triple-buffered h; per-step sync = DSMEM mbarrier (32 storer lanes arrive on all
// 4 CTAs' barriers with release.cluster; everyone acquire-waits locally).
#define CLUSTER  4
#define B_TILE   2
#define NTHREADS 512
#define UNITSL   64
#define ROWSL    192
#define WH_PAD   260       // 256 cols contiguous + 4 end-pad (row stride mod 32 = 4)
#define HB_PAD   268       // 256 cols contiguous + 12 end-pad
#define NBUF     3
#define HBYTES   (B_TILE * HB_PAD * 4)   // byte stride between h buffers
#define MBAR_CNT 128                     // 32 storer lanes x 4 CTAs
#define PARTS    8

// Precomputed encoder input gates: gi[t*64 + b][grow], grow = gate*256 + U0 + u
__device__ float g_gi[(size_t)Lseq * 64 * GI3H];   // 201 MB scratch

struct __align__(16) Smem {
    float Wh[ROWSL * WH_PAD];        // 192x256 weight slice (enc Whh -> dec Wih -> dec Whh)
    float hb[NBUF][B_TILE][HB_PAD];  // triple-buffered hidden state
    float wa[Hdim];                  // attention hidden weight row
    float wdec[Hdim];                // decoder output weight
    float yb[Lseq * B_TILE];         // decoder outputs
    float red[768];                  // staging: context / final GEMM reduction
    unsigned long long mbar;         // per-step cluster mbarrier
};

__device__ __forceinline__ uint32_t s2u(const void* p) {
    uint32_t a;
    asm("{ .reg .u64 t; cvta.to.shared.u64 t, %1; cvt.u32.u64 %0, t; }"
        : "=r"(a) : "l"(p));
    return a;
}

__device__ __forceinline__ uint32_t mapa_r(uint32_t la, int r) {
    uint32_t ra;
    asm("mapa.shared::cluster.u32 %0, %1, %2;" : "=r"(ra) : "r"(la), "r"(r));
    return ra;
}

__device__ __forceinline__ void st_clu64(uint32_t ra, float a, float b) {
    unsigned long long v;
    asm("mov.b64 %0, {%1, %2};" : "=l"(v)
        : "r"(__float_as_uint(a)), "r"(__float_as_uint(b)));
    asm volatile("st.shared::cluster.b64 [%0], %1;" :: "r"(ra), "l"(v) : "memory");
}

__device__ __forceinline__ void csync() {
    asm volatile("barrier.cluster.arrive.aligned;" ::: "memory");
    asm volatile("barrier.cluster.wait.aligned;" ::: "memory");
}

__device__ __forceinline__ void mbar_init(uint32_t a, uint32_t cnt) {
    asm volatile("mbarrier.init.shared.b64 [%0], %1;" :: "r"(a), "r"(cnt) : "memory");
}

// Remote arrive with release at cluster scope (covers this thread's prior stores).
__device__ __forceinline__ void mbar_arrive_rel(uint32_t ra) {
    asm volatile("mbarrier.arrive.release.cluster.shared::cluster.b64 _, [%0];"
                 :: "r"(ra) : "memory");
}

// Acquire-wait (cluster scope) on local mbarrier for phase parity `ph`.
__device__ __forceinline__ void mbar_wait(uint32_t a, uint32_t ph) {
    uint32_t done;
    asm volatile(
        "{\n\t.reg .pred p;\n\t"
        "mbarrier.try_wait.parity.acquire.cluster.shared::cta.b64 p, [%1], %2, 0x989680;\n\t"
        "selp.b32 %0, 1, 0, p;\n\t}"
        : "=r"(done) : "r"(a), "r"(ph) : "memory");
    while (!done) {
        asm volatile(
            "{\n\t.reg .pred p;\n\t"
            "mbarrier.try_wait.parity.acquire.cluster.shared::cta.b64 p, [%1], %2, 0x989680;\n\t"
            "selp.b32 %0, 1, 0, p;\n\t}"
            : "=r"(done) : "r"(a), "r"(ph) : "memory");
    }
}

// sigmoid via single MUFU.TANH
__device__ __forceinline__ float sigf(float v) {
    return 0.5f * tanhf(0.5f * v) + 0.5f;
}

#define FMA2(acc, w, h) \
    asm("fma.rn.f32x2 %0, %1, %2, %0;" : "+l"(acc) : "l"(w), "l"(h))

__device__ __forceinline__ float ps(unsigned long long a) {
    return __uint_as_float((unsigned)(a & 0xffffffffull))
         + __uint_as_float((unsigned)(a >> 32));
}

// Fused 3-row, 2-batch octant dot with bank rotation; full reduce + batch fold.
// Returns the 3 gate sums for the thread's primary batch (o>>2).
__device__ __forceinline__ void dot3b(const float* __restrict__ wp0,
                                      const float* __restrict__ wp1,
                                      const float* __restrict__ wp2,
                                      const float* __restrict__ h0,
                                      const float* __restrict__ h1,
                                      int o,
                                      float& s0, float& s1, float& s2) {
    unsigned long long A00=0, A01=0, A10=0, A11=0, A20=0, A21=0;
#pragma unroll
    for (int c = 0; c < 8; c++) {
        int off = 4 * ((o + c) & 7);            // bank-rotated chunk within octant
        ulonglong2 ha = *(const ulonglong2*)(h0 + off);
        ulonglong2 hc = *(const ulonglong2*)(h1 + off);
        ulonglong2 w  = *(const ulonglong2*)(wp0 + off);
        FMA2(A00, w.x, ha.x);  FMA2(A00, w.y, ha.y);
        FMA2(A01, w.x, hc.x);  FMA2(A01, w.y, hc.y);
        w = *(const ulonglong2*)(wp1 + off);
        FMA2(A10, w.x, ha.x);  FMA2(A10, w.y, ha.y);
        FMA2(A11, w.x, hc.x);  FMA2(A11, w.y, hc.y);
        w = *(const ulonglong2*)(wp2 + off);
        FMA2(A20, w.x, ha.x);  FMA2(A20, w.y, ha.y);
        FMA2(A21, w.x, hc.x);  FMA2(A21, w.y, hc.y);
    }
    float p00 = ps(A00), p01 = ps(A01);
    float p10 = ps(A10), p11 = ps(A11);
    float p20 = ps(A20), p21 = ps(A21);
    const bool lo = (o < 4);
    float t0 = lo ? p01 : p00;
    float t1 = lo ? p11 : p10;
    float t2 = lo ? p21 : p20;
    t0 = __shfl_xor_sync(0xffffffffu, t0, 4);
    t1 = __shfl_xor_sync(0xffffffffu, t1, 4);
    t2 = __shfl_xor_sync(0xffffffffu, t2, 4);
    s0 = (lo ? p00 : p01) + t0;
    s1 = (lo ? p10 : p11) + t1;
    s2 = (lo ? p20 : p21) + t2;
    s0 += __shfl_xor_sync(0xffffffffu, s0, 1);
    s0 += __shfl_xor_sync(0xffffffffu, s0, 2);
    s1 += __shfl_xor_sync(0xffffffffu, s1, 1);
    s1 += __shfl_xor_sync(0xffffffffu, s1, 2);
    s2 += __shfl_xor_sync(0xffffffffu, s2, 1);
    s2 += __shfl_xor_sync(0xffffffffu, s2, 2);
}

// ---------------- Pre-kernel: gi[t][b][o] = b_ih_e[o] + x[b,t,:] . W_ih_e[o,:] ----
__global__ void __launch_bounds__(256, 1)
gi_kernel(const float* __restrict__ x,
          const float* __restrict__ Wihe,
          const float* __restrict__ bihe)
{
    __shared__ float xs[64 * Pdim];
    const int t = blockIdx.x;
    const int o = blockIdx.y * 256 + threadIdx.x;

    float4 wr[16];
    const float4* Wr = (const float4*)(Wihe + o * Pdim);
#pragma unroll
    for (int k = 0; k < 16; k++) wr[k] = Wr[k];
    const float bia = bihe[o];

    for (int idx = threadIdx.x; idx < 64 * Pdim; idx += 256) {
        int b = idx >> 6, p = idx & 63;
        xs[idx] = x[((size_t)b * Lseq + t) * Pdim + p];
    }
    __syncthreads();

    for (int b = 0; b < 64; b++) {
        const float4* xr = (const float4*)(xs + b * Pdim);
        float a0 = bia, a1 = 0.f, a2 = 0.f, a3 = 0.f;
#pragma unroll
        for (int k = 0; k < 16; k++) {
            float4 w = wr[k], xx = xr[k];
            a0 = fmaf(w.x, xx.x, a0); a1 = fmaf(w.y, xx.y, a1);
            a2 = fmaf(w.z, xx.z, a2); a3 = fmaf(w.w, xx.w, a3);
        }
        g_gi[((size_t)t * 64 + b) * GI3H + o] = (a0 + a1) + (a2 + a3);
    }
}

// ---------------- Main recurrent kernel ----------------
__global__ void __cluster_dims__(CLUSTER, 1, 1) __launch_bounds__(NTHREADS, 1)
attn_net_kernel(const float* __restrict__ x,
                const float* __restrict__ Wihe, const float* __restrict__ Whhe,
                const float* __restrict__ bihe, const float* __restrict__ bhhe,
                const float* __restrict__ Wihd, const float* __restrict__ Whhd,
                const float* __restrict__ bihd, const float* __restrict__ bhhd,
                const float* __restrict__ Wdec, const float* __restrict__ bdec_p,
                const float* __restrict__ Wattn, const float* __restrict__ battn,
                const float* __restrict__ Wout, const float* __restrict__ bout,
                float* __restrict__ out)
{
    extern __shared__ char smem_raw[];
    Smem& S = *reinterpret_cast<Smem*>(smem_raw);

    const int tid = threadIdx.x;
    uint32_t rank;
    asm("mov.u32 %0, %%cluster_ctarank;" : "=r"(rank));
    const int g   = blockIdx.x >> 2;             // cluster id 0..31
    const int b0  = g * B_TILE;
    const int U0  = (int)rank * UNITSL;
    const int u   = tid >> 3;                    // unit 0..63
    const int o   = tid & 7;                     // octant 0..7
    const int pb  = o >> 2;                      // primary batch 0/1
    const bool storer = ((o & 3) == 0) && ((u & 3) == 0);  // o in {0,4}, u%4==0

    const float* wp0 = &S.Wh[u * WH_PAD + o * 32];
    const float* wp1 = wp0 + 64 * WH_PAD;
    const float* wp2 = wp0 + 128 * WH_PAD;
    const int hoff = o * 32;
    const uint32_t mb_local = s2u(&S.mbar);

    // ---------------- Phase 0: encoder recurrent weights ----------------
    for (int idx = tid; idx < ROWSL * Hdim; idx += NTHREADS) {
        int lr = idx >> 8, k = idx & 255;
        int grow = (lr >> 6) * Hdim + U0 + (lr & 63);
        S.Wh[lr * WH_PAD + k] = Whhe[grow * Hdim + k];
    }
    for (int idx = tid; idx < Hdim; idx += NTHREADS) {
        S.wa[idx]   = Wattn[Hdim + idx];
        S.wdec[idx] = Wdec[idx];
    }
    for (int idx = tid; idx < NBUF * B_TILE * HB_PAD; idx += NTHREADS)
        ((float*)S.hb)[idx] = 0.f;
    if (tid == 0) mbar_init(mb_local, MBAR_CNT);

    float bg0 = bhhe[U0 + u];
    float bg1 = bhhe[Hdim + U0 + u];
    float bg2 = bhhe[2 * Hdim + U0 + u];
    __syncthreads();
    csync();    // all CTAs' mbarriers initialized before any arrive

    // Remote DSMEM base addresses (h buffer 0 + mbarrier) for store lanes
    uint32_t rbase[CLUSTER], rbar[CLUSTER];
    if (storer) {
        uint32_t la = s2u(&S.hb[0][pb][U0 + u]);
#pragma unroll
        for (int pr = 0; pr < CLUSTER; pr++) {
            rbase[pr] = mapa_r(la, pr);
            rbar[pr]  = mapa_r(mb_local, pr);
        }
    }

    // gi prefetch for primary batch (one step ahead); h carried in register
    const float* giP = g_gi + (size_t)(b0 + pb) * GI3H + U0 + u;
    float g0 = giP[0], g1 = giP[256], g2 = giP[512];
    float hprev = 0.f;

    // Warps 0-1 = batches 0-1: online-softmax state
    float m_run = -3.0e38f, Z_run = 0.f, C0 = 0.f, C1 = 0.f;

    uint32_t ph = 0;   // mbarrier phase parity, continuous across both loops

    // ---------------- Phase 1: encoder GRU + delayed online-softmax attention ----
    int cur = 0;
    for (int t = 0; t < Lseq; t++) {
        int nxt = cur + 1; if (nxt == NBUF) nxt = 0;

        float n0 = 0.f, n1 = 0.f, n2 = 0.f;
        if ((t + 1) < Lseq) {
            const float* p = giP + (size_t)(t + 1) * (64 * GI3H);
            n0 = p[0]; n1 = p[256]; n2 = p[512];
        }

        float s0, s1, s2;
        dot3b(wp0, wp1, wp2,
              &S.hb[cur][0][hoff], &S.hb[cur][1][hoff], o, s0, s1, s2);

        float r  = sigf(g0 + bg0 + s0);
        float z  = sigf(g1 + bg1 + s1);
        float nn = tanhf(g2 + r * (bg2 + s2));
        float hn = nn + z * (hprev - nn);
        hprev = hn;
        g0 = n0; g1 = n1; g2 = n2;

        // pack 4 units (same o), broadcast into buffer nxt of all 4 CTAs, arrive
        float v1 = __shfl_down_sync(0xffffffffu, hn, 8);
        float v2 = __shfl_down_sync(0xffffffffu, hn, 16);
        float v3 = __shfl_down_sync(0xffffffffu, hn, 24);
        if (storer) {
            uint32_t boff = (uint32_t)(nxt * HBYTES);
#pragma unroll
            for (int pr = 0; pr < CLUSTER; pr++) {
                st_clu64(rbase[pr] + boff,     hn, v1);
                st_clu64(rbase[pr] + boff + 8, v2, v3);
            }
#pragma unroll
            for (int pr = 0; pr < CLUSTER; pr++)
                mbar_arrive_rel(rbar[pr]);
        }

        // Delayed attention on h_t = buf[cur] (skip t=0: h_0 = 0 state).
        // buf[cur] is not overwritten by peers until step t+2 (triple buffering).
        if (t > 0 && tid < 64) {
            int w = tid >> 5, l = tid & 31;
            const float* hr = S.hb[cur][w];
            float p = 0.f;
#pragma unroll
            for (int j = l; j < 256; j += 32) p += hr[j] * S.wa[j];
#pragma unroll
            for (int ofs = 16; ofs > 0; ofs >>= 1) p += __shfl_xor_sync(0xffffffffu, p, ofs);
            float mn  = fmaxf(m_run, p);
            float sc  = expf(m_run - mn);
            float wgt = expf(p - mn);
            Z_run = Z_run * sc + wgt;
            m_run = mn;
            C0 = C0 * sc + wgt * hr[U0 + l];
            C1 = C1 * sc + wgt * hr[U0 + 32 + l];
        }
        mbar_wait(mb_local, ph);
        ph ^= 1;
        cur = nxt;
    }
    // h_1024 lives in buf[cur] (cur == 1024 % 3 == 1)

    // Tail: accumulate the last state h_1024 into the softmax
    if (tid < 64) {
        int w = tid >> 5, l = tid & 31;
        const float* hr = S.hb[cur][w];
        float p = 0.f;
#pragma unroll
        for (int j = l; j < 256; j += 32) p += hr[j] * S.wa[j];
#pragma unroll
        for (int ofs = 16; ofs > 0; ofs >>= 1) p += __shfl_xor_sync(0xffffffffu, p, ofs);
        float mn  = fmaxf(m_run, p);
        float sc  = expf(m_run - mn);
        float wgt = expf(p - mn);
        Z_run = Z_run * sc + wgt;
        m_run = mn;
        C0 = C0 * sc + wgt * hr[U0 + l];
        C1 = C1 * sc + wgt * hr[U0 + 32 + l];
    }

    // ---------------- Phase 1.5: context c -> buf[2]; s0 -> buf[0] ----------------
    __syncthreads();
    if (tid < 64) {
        int w = tid >> 5, l = tid & 31;
        float iz = 1.f / Z_run;
        S.red[w * 64 + l]      = C0 * iz;
        S.red[w * 64 + 32 + l] = C1 * iz;
    }
    // copy s0 = h_1024 (buf[cur]) into buf[0] locally (every CTA holds full h)
    for (int idx = tid; idx < B_TILE * HB_PAD; idx += NTHREADS)
        ((float*)S.hb[0])[idx] = ((const float*)S.hb[cur])[idx];
    __syncthreads();
    if (storer) {
        float c0 = S.red[pb * 64 + u],     c1 = S.red[pb * 64 + u + 1];
        float c2 = S.red[pb * 64 + u + 2], c3 = S.red[pb * 64 + u + 3];
        uint32_t boff = (uint32_t)(2 * HBYTES);
#pragma unroll
        for (int pr = 0; pr < CLUSTER; pr++) {
            st_clu64(rbase[pr] + boff,     c0, c1);
            st_clu64(rbase[pr] + boff + 8, c2, c3);
        }
    }
    csync();

    // decoder input weights; giD = W_ih_d . c + b_ih_d (registers, primary batch)
    for (int idx = tid; idx < ROWSL * Hdim; idx += NTHREADS) {
        int lr = idx >> 8, k = idx & 255;
        int grow = (lr >> 6) * Hdim + U0 + (lr & 63);
        S.Wh[lr * WH_PAD + k] = Wihd[grow * Hdim + k];
    }
    __syncthreads();
    float gid0, gid1, gid2;
    {
        float s0, s1, s2;
        dot3b(wp0, wp1, wp2,
              &S.hb[2][0][hoff], &S.hb[2][1][hoff], o, s0, s1, s2);
        gid0 = bihd[U0 + u] + s0;
        gid1 = bihd[Hdim + U0 + u] + s1;
        gid2 = bihd[2 * Hdim + U0 + u] + s2;
    }
    __syncthreads();

    // decoder recurrent weights + biases
    for (int idx = tid; idx < ROWSL * Hdim; idx += NTHREADS) {
        int lr = idx >> 8, k = idx & 255;
        int grow = (lr >> 6) * Hdim + U0 + (lr & 63);
        S.Wh[lr * WH_PAD + k] = Whhd[grow * Hdim + k];
    }
    bg0 = bhhd[U0 + u];
    bg1 = bhhd[Hdim + U0 + u];
    bg2 = bhhd[2 * Hdim + U0 + u];
    const float bdec = bdec_p[0];
    __syncthreads();
    csync();

    // ---------------- Phase 2: decoder GRU (constant input gates, delayed y) ----
    cur = 0;
    for (int i = 0; i < Lseq; i++) {
        int nxt = cur + 1; if (nxt == NBUF) nxt = 0;

        float s0, s1, s2;
        dot3b(wp0, wp1, wp2,
              &S.hb[cur][0][hoff], &S.hb[cur][1][hoff], o, s0, s1, s2);

        float r  = sigf(gid0 + bg0 + s0);
        float z  = sigf(gid1 + bg1 + s1);
        float nn = tanhf(gid2 + r * (bg2 + s2));
        float sn = nn + z * (hprev - nn);
        hprev = sn;

        float v1 = __shfl_down_sync(0xffffffffu, sn, 8);
        float v2 = __shfl_down_sync(0xffffffffu, sn, 16);
        float v3 = __shfl_down_sync(0xffffffffu, sn, 24);
        if (storer) {
            uint32_t boff = (uint32_t)(nxt * HBYTES);
#pragma unroll
            for (int pr = 0; pr < CLUSTER; pr++) {
                st_clu64(rbase[pr] + boff,     sn, v1);
                st_clu64(rbase[pr] + boff + 8, v2, v3);
            }
#pragma unroll
            for (int pr = 0; pr < CLUSTER; pr++)
                mbar_arrive_rel(rbar[pr]);
        }

        // Delayed y: y_{i-1} = sigmoid(s_i . w_dec + b_dec), s_i = buf[cur]
        if (i > 0 && tid < 64) {
            int w = tid >> 5, l = tid & 31;
            const float* hr = S.hb[cur][w];
            float p = 0.f;
#pragma unroll
            for (int j = l; j < 256; j += 32) p += hr[j] * S.wdec[j];
#pragma unroll
            for (int ofs = 16; ofs > 0; ofs >>= 1) p += __shfl_xor_sync(0xffffffffu, p, ofs);
            if (l == 0) S.yb[(i - 1) * 2 + w] = sigf(p + bdec);
        }
        mbar_wait(mb_local, ph);
        ph ^= 1;
        cur = nxt;
    }
    // Tail: y_1023 from s_1024 = buf[cur]
    if (tid < 64) {
        int w = tid >> 5, l = tid & 31;
        const float* hr = S.hb[cur][w];
        float p = 0.f;
#pragma unroll
        for (int j = l; j < 256; j += 32) p += hr[j] * S.wdec[j];
#pragma unroll
        for (int ofs = 16; ofs > 0; ofs >>= 1) p += __shfl_xor_sync(0xffffffffu, p, ofs);
        if (l == 0) S.yb[(Lseq - 1) * 2 + w] = sigf(p + bdec);
    }

    // ---------------- Phase 3: out = y @ W_out^T + b_out ----------------
    __syncthreads();
    {
        int part = tid >> 6;                // 0..7
        int ob   = tid & 63;                // 32 o-rows x 2 batches
        int orow = (int)rank * 32 + (ob >> 1);
        int b    = ob & 1;
        float acc = 0.f;
        for (int i = part; i < Lseq; i += PARTS)
            acc += S.yb[i * 2 + b] * Wout[orow * Lseq + i];
        S.red[ob * PARTS + part] = acc;
    }
    __syncthreads();
    if (tid < 64) {
        int orow = (int)rank * 32 + (tid >> 1);
        int b    = tid & 1;
        float s  = bout[orow];
#pragma unroll
        for (int p8 = 0; p8 < PARTS; p8++) s += S.red[tid * PARTS + p8];
        out[(b0 + b) * OUTD + orow] = s;
    }
}

extern "C" void kernel_launch(void* const* d_in, const int* in_sizes, int n_in,
                              void* d_out, int out_size) {
    (void)in_sizes; (void)n_in; (void)out_size;

    // Pre-kernel: gi = x @ W_ih_e^T + b_ih_e for all timesteps
    gi_kernel<<<dim3(Lseq, 3), 256>>>(
        (const float*)d_in[0], (const float*)d_in[1], (const float*)d_in[3]);

    cudaFuncSetAttribute(attn_net_kernel,
                         cudaFuncAttributeMaxDynamicSharedMemorySize,
                         (int)sizeof(Smem));
    attn_net_kernel<<<128, NTHREADS, sizeof(Smem)>>>(
        (const float*)d_in[0],  (const float*)d_in[1],  (const float*)d_in[2],
        (const float*)d_in[3],  (const float*)d_in[4],  (const float*)d_in[5],
        (const float*)d_in[6],  (const float*)d_in[7],  (const float*)d_in[8],
        (const float*)d_in[9],  (const float*)d_in[10], (const float*)d_in[11],
        (const float*)d_in[12], (const float*)d_in[13], (const float*)d_in[14],
        (float*)d_out);
}

// round 17
// speedup vs baseline: 2.1780x; 2.1780x over previous
#include <cuda_runtime.h>
#include <cstdint>

// Problem dims
#define Lseq  1024
#define Pdim  64
#define Hdim  256
#define OUTD  128
#define GI3H  768      // 3*Hdim

// 32 clusters x 4 CTAs. Cluster: 2 batch rows. CTA: 64 hidden units (192 gate rows).
// 256 threads: tid = u*4 + oc. Thread holds its 3 gate rows x 64-col octant of the
// recurrent weight matrix IN REGISTERS (96 ulonglong2 = f32x2 pairs), computes both
// batches, folds batch via shfl_xor(2) (lanes oc<2 own batch0), finishes octant
// reduce with shfl_xor(1). h stored octant-padded (68-float stride) -> conflict-free
// static-index LDS. Triple-buffered h + split cluster arrive/wait with delayed
// attention/y inside the barrier window.
#define CLUSTER  4
#define B_TILE   2
#define NTHREADS 256
#define UNITSL   64
#define HOCT     68                      // padded octant stride (64 + 4)
#define HB_PAD   (4 * HOCT)              // 272 floats per (buf, batch)
#define NBUF     3
#define HBYTES   (B_TILE * HB_PAD * 4)   // byte stride between h buffers
#define PARTS    4

// Precomputed encoder input gates: gi[t*64 + b][grow], grow = gate*256 + U0 + u
__device__ float g_gi[(size_t)Lseq * 64 * GI3H];   // 201 MB scratch

struct __align__(16) Smem {
    float hb[NBUF][B_TILE][HB_PAD];  // triple-buffered hidden state (octant-padded)
    float wa[Hdim];                  // attention hidden weight row
    float wdec[Hdim];                // decoder output weight
    float yb[Lseq * B_TILE];         // decoder outputs
    float red[768];                  // staging: context / final GEMM reduction
};

__device__ __forceinline__ uint32_t s2u(const void* p) {
    uint32_t a;
    asm("{ .reg .u64 t; cvta.to.shared.u64 t, %1; cvt.u32.u64 %0, t; }"
        : "=r"(a) : "l"(p));
    return a;
}

__device__ __forceinline__ uint32_t mapa_r(uint32_t la, int r) {
    uint32_t ra;
    asm("mapa.shared::cluster.u32 %0, %1, %2;" : "=r"(ra) : "r"(la), "r"(r));
    return ra;
}

__device__ __forceinline__ void st_clu64(uint32_t ra, float a, float b) {
    unsigned long long v;
    asm("mov.b64 %0, {%1, %2};" : "=l"(v)
        : "r"(__float_as_uint(a)), "r"(__float_as_uint(b)));
    asm volatile("st.shared::cluster.b64 [%0], %1;" :: "r"(ra), "l"(v) : "memory");
}

__device__ __forceinline__ void carrive() {
    asm volatile("barrier.cluster.arrive.aligned;" ::: "memory");
}
__device__ __forceinline__ void cwait() {
    asm volatile("barrier.cluster.wait.aligned;" ::: "memory");
}
__device__ __forceinline__ void csync() { carrive(); cwait(); }

// sigmoid via single MUFU.TANH
__device__ __forceinline__ float sigf(float v) {
    return 0.5f * tanhf(0.5f * v) + 0.5f;
}

#define FMA2(acc, w, h) \
    asm("fma.rn.f32x2 %0, %1, %2, %0;" : "+l"(acc) : "l"(w), "l"(h))

__device__ __forceinline__ float ps(unsigned long long a) {
    return __uint_as_float((unsigned)(a & 0xffffffffull))
         + __uint_as_float((unsigned)(a >> 32));
}

// Load this thread's 3 gate rows x 64-col octant into registers (f32x2 packed).
__device__ __forceinline__ void loadW(unsigned long long (&W)[96],
                                      const float* __restrict__ src,
                                      int U0, int u, int oc) {
#pragma unroll
    for (int gq = 0; gq < 3; gq++) {
        const ulonglong2* p =
            (const ulonglong2*)(src + (size_t)(gq * Hdim + U0 + u) * Hdim + oc * 64);
#pragma unroll
        for (int c = 0; c < 16; c++) {
            ulonglong2 v = p[c];
            W[gq * 32 + 2 * c]     = v.x;
            W[gq * 32 + 2 * c + 1] = v.y;
        }
    }
}

// Register-weight octant dot over both batches; batch fold + octant reduce.
// Returns the 3 gate sums for the thread's primary batch (oc>>1).
__device__ __forceinline__ void dotreg(const unsigned long long (&W)[96],
                                       const float* __restrict__ h0,
                                       const float* __restrict__ h1,
                                       bool lo,
                                       float& s0, float& s1, float& s2) {
    unsigned long long A00=0, A01=0, A10=0, A11=0, A20=0, A21=0;
#pragma unroll
    for (int c = 0; c < 16; c++) {
        ulonglong2 ha = *(const ulonglong2*)(h0 + 4 * c);
        ulonglong2 hc = *(const ulonglong2*)(h1 + 4 * c);
        FMA2(A00, W[2*c],      ha.x);  FMA2(A00, W[2*c+1],      ha.y);
        FMA2(A01, W[2*c],      hc.x);  FMA2(A01, W[2*c+1],      hc.y);
        FMA2(A10, W[32+2*c],   ha.x);  FMA2(A10, W[32+2*c+1],   ha.y);
        FMA2(A11, W[32+2*c],   hc.x);  FMA2(A11, W[32+2*c+1],   hc.y);
        FMA2(A20, W[64+2*c],   ha.x);  FMA2(A20, W[64+2*c+1],   ha.y);
        FMA2(A21, W[64+2*c],   hc.x);  FMA2(A21, W[64+2*c+1],   hc.y);
    }
    float p00 = ps(A00), p01 = ps(A01);
    float p10 = ps(A10), p11 = ps(A11);
    float p20 = ps(A20), p21 = ps(A21);
    // fold non-primary batch across (oc, oc^2), then octant pair (oc, oc^1)
    float t0 = lo ? p01 : p00;
    float t1 = lo ? p11 : p10;
    float t2 = lo ? p21 : p20;
    t0 = __shfl_xor_sync(0xffffffffu, t0, 2);
    t1 = __shfl_xor_sync(0xffffffffu, t1, 2);
    t2 = __shfl_xor_sync(0xffffffffu, t2, 2);
    s0 = (lo ? p00 : p01) + t0;
    s1 = (lo ? p10 : p11) + t1;
    s2 = (lo ? p20 : p21) + t2;
    s0 += __shfl_xor_sync(0xffffffffu, s0, 1);
    s1 += __shfl_xor_sync(0xffffffffu, s1, 1);
    s2 += __shfl_xor_sync(0xffffffffu, s2, 1);
}

// ---------------- Pre-kernel: gi[t][b][o] = b_ih_e[o] + x[b,t,:] . W_ih_e[o,:] ----
__global__ void __launch_bounds__(256, 1)
gi_kernel(const float* __restrict__ x,
          const float* __restrict__ Wihe,
          const float* __restrict__ bihe)
{
    __shared__ float xs[64 * Pdim];
    const int t = blockIdx.x;
    const int o = blockIdx.y * 256 + threadIdx.x;

    float4 wr[16];
    const float4* Wr = (const float4*)(Wihe + o * Pdim);
#pragma unroll
    for (int k = 0; k < 16; k++) wr[k] = Wr[k];
    const float bia = bihe[o];

    for (int idx = threadIdx.x; idx < 64 * Pdim; idx += 256) {
        int b = idx >> 6, p = idx & 63;
        xs[idx] = x[((size_t)b * Lseq + t) * Pdim + p];
    }
    __syncthreads();

    for (int b = 0; b < 64; b++) {
        const float4* xr = (const float4*)(xs + b * Pdim);
        float a0 = bia, a1 = 0.f, a2 = 0.f, a3 = 0.f;
#pragma unroll
        for (int k = 0; k < 16; k++) {
            float4 w = wr[k], xx = xr[k];
            a0 = fmaf(w.x, xx.x, a0); a1 = fmaf(w.y, xx.y, a1);
            a2 = fmaf(w.z, xx.z, a2); a3 = fmaf(w.w, xx.w, a3);
        }
        g_gi[((size_t)t * 64 + b) * GI3H + o] = (a0 + a1) + (a2 + a3);
    }
}

// ---------------- Main recurrent kernel ----------------
__global__ void __cluster_dims__(CLUSTER, 1, 1) __launch_bounds__(NTHREADS, 1)
attn_net_kernel(const float* __restrict__ x,
                const float* __restrict__ Wihe, const float* __restrict__ Whhe,
                const float* __restrict__ bihe, const float* __restrict__ bhhe,
                const float* __restrict__ Wihd, const float* __restrict__ Whhd,
                const float* __restrict__ bihd, const float* __restrict__ bhhd,
                const float* __restrict__ Wdec, const float* __restrict__ bdec_p,
                const float* __restrict__ Wattn, const float* __restrict__ battn,
                const float* __restrict__ Wout, const float* __restrict__ bout,
                float* __restrict__ out)
{
    extern __shared__ char smem_raw[];
    Smem& S = *reinterpret_cast<Smem*>(smem_raw);

    const int tid = threadIdx.x;
    uint32_t rank;
    asm("mov.u32 %0, %%cluster_ctarank;" : "=r"(rank));
    const int g   = blockIdx.x >> 2;             // cluster id 0..31
    const int b0  = g * B_TILE;
    const int U0  = (int)rank * UNITSL;
    const int u   = tid >> 2;                    // unit 0..63
    const int oc  = tid & 3;                     // octant 0..3
    const bool lo = (oc < 2);                    // primary batch = oc>>1
    const int pb  = oc >> 1;
    const bool storer = ((oc & 1) == 0) && ((u & 3) == 0);  // oc in {0,2}, u%4==0
    const int hoff = oc * HOCT;

    unsigned long long W[96];                    // register-resident weight slice

    // ---------------- Phase 0: setup ----------------
    loadW(W, Whhe, U0, u, oc);
    for (int idx = tid; idx < Hdim; idx += NTHREADS) {
        S.wa[idx]   = Wattn[Hdim + idx];
        S.wdec[idx] = Wdec[idx];
    }
    for (int idx = tid; idx < NBUF * B_TILE * HB_PAD; idx += NTHREADS)
        ((float*)S.hb)[idx] = 0.f;

    float bg0 = bhhe[U0 + u];
    float bg1 = bhhe[Hdim + U0 + u];
    float bg2 = bhhe[2 * Hdim + U0 + u];
    __syncthreads();
    csync();

    // Remote DSMEM base addresses (h buffer 0) for store lanes; padded unit index
    uint32_t rbase[CLUSTER];
    if (storer) {
        uint32_t la = s2u(&S.hb[0][pb][(int)rank * HOCT + u]);
#pragma unroll
        for (int pr = 0; pr < CLUSTER; pr++)
            rbase[pr] = mapa_r(la, pr);
    }

    // gi prefetch for primary batch (one step ahead); h carried in register
    const float* giP = g_gi + (size_t)(b0 + pb) * GI3H + U0 + u;
    float g0 = giP[0], g1 = giP[256], g2 = giP[512];
    float hprev = 0.f;

    // Warps 0-1 = batches 0-1: online-softmax state
    float m_run = -3.0e38f, Z_run = 0.f, C0 = 0.f, C1 = 0.f;

    // ---------------- Phase 1: encoder GRU + delayed online-softmax attention ----
    int cur = 0;
    for (int t = 0; t < Lseq; t++) {
        int nxt = cur + 1; if (nxt == NBUF) nxt = 0;

        float n0 = 0.f, n1 = 0.f, n2 = 0.f;
        if ((t + 1) < Lseq) {
            const float* p = giP + (size_t)(t + 1) * (64 * GI3H);
            n0 = p[0]; n1 = p[256]; n2 = p[512];
        }

        float s0, s1, s2;
        dotreg(W, &S.hb[cur][0][hoff], &S.hb[cur][1][hoff], lo, s0, s1, s2);

        float r  = sigf(g0 + bg0 + s0);
        float z  = sigf(g1 + bg1 + s1);
        float nn = tanhf(g2 + r * (bg2 + s2));
        float hn = nn + z * (hprev - nn);
        hprev = hn;
        g0 = n0; g1 = n1; g2 = n2;

        // pack 4 units (lanes stride 4), broadcast into buffer nxt of all 4 CTAs
        float v1 = __shfl_down_sync(0xffffffffu, hn, 4);
        float v2 = __shfl_down_sync(0xffffffffu, hn, 8);
        float v3 = __shfl_down_sync(0xffffffffu, hn, 12);
        if (storer) {
            uint32_t boff = (uint32_t)(nxt * HBYTES);
#pragma unroll
            for (int pr = 0; pr < CLUSTER; pr++) {
                st_clu64(rbase[pr] + boff,     hn, v1);
                st_clu64(rbase[pr] + boff + 8, v2, v3);
            }
        }
        carrive();

        // Delayed attention on h_t = buf[cur] (skip t=0: h_0 = 0 state).
        if (t > 0 && tid < 64) {
            int w = tid >> 5, l = tid & 31;
            const float* hr = S.hb[cur][w];
            float p = 0.f;
#pragma unroll
            for (int k = 0; k < 8; k++) {
                int idx = (k >> 1) * HOCT + ((k & 1) << 5) + l;
                p += hr[idx] * S.wa[k * 32 + l];
            }
#pragma unroll
            for (int ofs = 16; ofs > 0; ofs >>= 1) p += __shfl_xor_sync(0xffffffffu, p, ofs);
            float mn  = fmaxf(m_run, p);
            float sc  = expf(m_run - mn);
            float wgt = expf(p - mn);
            Z_run = Z_run * sc + wgt;
            m_run = mn;
            C0 = C0 * sc + wgt * hr[(int)rank * HOCT + l];
            C1 = C1 * sc + wgt * hr[(int)rank * HOCT + 32 + l];
        }
        cwait();
        cur = nxt;
    }
    // h_1024 lives in buf[cur]

    // Tail: accumulate the last state h_1024 into the softmax
    if (tid < 64) {
        int w = tid >> 5, l = tid & 31;
        const float* hr = S.hb[cur][w];
        float p = 0.f;
#pragma unroll
        for (int k = 0; k < 8; k++) {
            int idx = (k >> 1) * HOCT + ((k & 1) << 5) + l;
            p += hr[idx] * S.wa[k * 32 + l];
        }
#pragma unroll
        for (int ofs = 16; ofs > 0; ofs >>= 1) p += __shfl_xor_sync(0xffffffffu, p, ofs);
        float mn  = fmaxf(m_run, p);
        float sc  = expf(m_run - mn);
        float wgt = expf(p - mn);
        Z_run = Z_run * sc + wgt;
        m_run = mn;
        C0 = C0 * sc + wgt * hr[(int)rank * HOCT + l];
        C1 = C1 * sc + wgt * hr[(int)rank * HOCT + 32 + l];
    }

    // ---------------- Phase 1.5: context c -> buf[2]; s0 -> buf[0] ----------------
    __syncthreads();
    if (tid < 64) {
        int w = tid >> 5, l = tid & 31;
        float iz = 1.f / Z_run;
        S.red[w * 64 + l]      = C0 * iz;
        S.red[w * 64 + 32 + l] = C1 * iz;
    }
    // copy s0 = h_1024 (buf[cur]) into buf[0] locally
    for (int idx = tid; idx < B_TILE * HB_PAD; idx += NTHREADS)
        ((float*)S.hb[0])[idx] = ((const float*)S.hb[cur])[idx];
    __syncthreads();
    if (storer) {
        float c0 = S.red[pb * 64 + u],     c1 = S.red[pb * 64 + u + 1];
        float c2 = S.red[pb * 64 + u + 2], c3 = S.red[pb * 64 + u + 3];
        uint32_t boff = (uint32_t)(2 * HBYTES);
#pragma unroll
        for (int pr = 0; pr < CLUSTER; pr++) {
            st_clu64(rbase[pr] + boff,     c0, c1);
            st_clu64(rbase[pr] + boff + 8, c2, c3);
        }
    }
    csync();

    // decoder input weights -> regs; giD = W_ih_d . c + b_ih_d (primary batch)
    loadW(W, Wihd, U0, u, oc);
    float gid0, gid1, gid2;
    {
        float s0, s1, s2;
        dotreg(W, &S.hb[2][0][hoff], &S.hb[2][1][hoff], lo, s0, s1, s2);
        gid0 = bihd[U0 + u] + s0;
        gid1 = bihd[Hdim + U0 + u] + s1;
        gid2 = bihd[2 * Hdim + U0 + u] + s2;
    }

    // decoder recurrent weights -> regs; biases
    loadW(W, Whhd, U0, u, oc);
    bg0 = bhhd[U0 + u];
    bg1 = bhhd[Hdim + U0 + u];
    bg2 = bhhd[2 * Hdim + U0 + u];
    const float bdec = bdec_p[0];
    __syncthreads();
    csync();

    // ---------------- Phase 2: decoder GRU (constant input gates, delayed y) ----
    cur = 0;
    for (int i = 0; i < Lseq; i++) {
        int nxt = cur + 1; if (nxt == NBUF) nxt = 0;

        float s0, s1, s2;
        dotreg(W, &S.hb[cur][0][hoff], &S.hb[cur][1][hoff], lo, s0, s1, s2);

        float r  = sigf(gid0 + bg0 + s0);
        float z  = sigf(gid1 + bg1 + s1);
        float nn = tanhf(gid2 + r * (bg2 + s2));
        float sn = nn + z * (hprev - nn);
        hprev = sn;

        float v1 = __shfl_down_sync(0xffffffffu, sn, 4);
        float v2 = __shfl_down_sync(0xffffffffu, sn, 8);
        float v3 = __shfl_down_sync(0xffffffffu, sn, 12);
        if (storer) {
            uint32_t boff = (uint32_t)(nxt * HBYTES);
#pragma unroll
            for (int pr = 0; pr < CLUSTER; pr++) {
                st_clu64(rbase[pr] + boff,     sn, v1);
                st_clu64(rbase[pr] + boff + 8, v2, v3);
            }
        }
        carrive();

        // Delayed y: y_{i-1} = sigmoid(s_i . w_dec + b_dec), s_i = buf[cur]
        if (i > 0 && tid < 64) {
            int w = tid >> 5, l = tid & 31;
            const float* hr = S.hb[cur][w];
            float p = 0.f;
#pragma unroll
            for (int k = 0; k < 8; k++) {
                int idx = (k >> 1) * HOCT + ((k & 1) << 5) + l;
                p += hr[idx] * S.wdec[k * 32 + l];
            }
#pragma unroll
            for (int ofs = 16; ofs > 0; ofs >>= 1) p += __shfl_xor_sync(0xffffffffu, p, ofs);
            if (l == 0) S.yb[(i - 1) * 2 + w] = sigf(p + bdec);
        }
        cwait();
        cur = nxt;
    }
    // Tail: y_1023 from s_1024 = buf[cur]
    if (tid < 64) {
        int w = tid >> 5, l = tid & 31;
        const float* hr = S.hb[cur][w];
        float p = 0.f;
#pragma unroll
        for (int k = 0; k < 8; k++) {
            int idx = (k >> 1) * HOCT + ((k & 1) << 5) + l;
            p += hr[idx] * S.wdec[k * 32 + l];
        }
#pragma unroll
        for (int ofs = 16; ofs > 0; ofs >>= 1) p += __shfl_xor_sync(0xffffffffu, p, ofs);
        if (l == 0) S.yb[(Lseq - 1) * 2 + w] = sigf(p + bdec);
    }

    // ---------------- Phase 3: out = y @ W_out^T + b_out ----------------
    __syncthreads();
    {
        int part = tid >> 6;                // 0..3 K-split
        int ob   = tid & 63;                // 32 o-rows x 2 batches
        int orow = (int)rank * 32 + (ob >> 1);
        int b    = ob & 1;
        float acc = 0.f;
        for (int i = part; i < Lseq; i += PARTS)
            acc += S.yb[i * 2 + b] * Wout[orow * Lseq + i];
        S.red[ob * PARTS + part] = acc;
    }
    __syncthreads();
    if (tid < 64) {
        int orow = (int)rank * 32 + (tid >> 1);
        int b    = tid & 1;
        float s  = bout[orow];
#pragma unroll
        for (int p4 = 0; p4 < PARTS; p4++) s += S.red[tid * PARTS + p4];
        out[(b0 + b) * OUTD + orow] = s;
    }
}

extern "C" void kernel_launch(void* const* d_in, const int* in_sizes, int n_in,
                              void* d_out, int out_size) {
    (void)in_sizes; (void)n_in; (void)out_size;

    // Pre-kernel: gi = x @ W_ih_e^T + b_ih_e for all timesteps
    gi_kernel<<<dim3(Lseq, 3), 256>>>(
        (const float*)d_in[0], (const float*)d_in[1], (const float*)d_in[3]);

    cudaFuncSetAttribute(attn_net_kernel,
                         cudaFuncAttributeMaxDynamicSharedMemorySize,
                         (int)sizeof(Smem));
    attn_net_kernel<<<128, NTHREADS, sizeof(Smem)>>>(
        (const float*)d_in[0],  (const float*)d_in[1],  (const float*)d_in[2],
        (const float*)d_in[3],  (const float*)d_in[4],  (const float*)d_in[5],
        (const float*)d_in[6],  (const float*)d_in[7],  (const float*)d_in[8],
        (const float*)d_in[9],  (const float*)d_in[10], (const float*)d_in[11],
        (const float*)d_in[12], (const float*)d_in[13], (const float*)d_in[14],
        (float*)d_out);
}